// round 10
// baseline (speedup 1.0000x reference)
#include <cuda_runtime.h>
#include <cuda_bf16.h>
#include <cstdint>

#define B_ 4
#define T_ 2048
#define C_ 1024
#define H_ 16
#define HD_ 64
#define QKVC (3 * C_)
#define BT (B_ * T_)

// ---------------- scratch (no cudaMalloc allowed) ----------------
__device__ float g_qkv[(size_t)BT * QKVC];                 // 96 MB fp32
__device__ float g_y[(size_t)BT * C_];                     // 32 MB fp32
__device__ __nv_bfloat16 g_xh[(size_t)BT * C_];            // activation split (reused for y)
__device__ __nv_bfloat16 g_xl[(size_t)BT * C_];
__device__ __nv_bfloat16 g_wah[(size_t)QKVC * C_];         // W_attn^T split [3072][1024]
__device__ __nv_bfloat16 g_wal[(size_t)QKVC * C_];
__device__ __nv_bfloat16 g_wph[(size_t)C_ * C_];           // W_proj^T split [1024][1024]
__device__ __nv_bfloat16 g_wpl[(size_t)C_ * C_];

__device__ __forceinline__ uint32_t smem_u32(const void* p) {
    return (uint32_t)__cvta_generic_to_shared(p);
}

// warp-level tensor core ops (sm_80-era PTX -> legal on plain sm_103 target)
#define LDSM_X4(r0, r1, r2, r3, addr) \
    asm volatile("ldmatrix.sync.aligned.m8n8.x4.shared.b16 {%0,%1,%2,%3}, [%4];" \
        : "=r"(r0), "=r"(r1), "=r"(r2), "=r"(r3) : "r"(addr))

#define MMA_BF16(D, a0, a1, a2, a3, b0, b1) \
    asm volatile("mma.sync.aligned.m16n8k16.row.col.f32.bf16.bf16.f32 " \
        "{%0,%1,%2,%3}, {%4,%5,%6,%7}, {%8,%9}, {%0,%1,%2,%3};" \
        : "+f"((D)[0]), "+f"((D)[1]), "+f"((D)[2]), "+f"((D)[3]) \
        : "r"(a0), "r"(a1), "r"(a2), "r"(a3), "r"(b0), "r"(b1))

// ---------------------------------------------------------------------------
// fp32 -> bf16 hi/lo split (elementwise)
// ---------------------------------------------------------------------------
__global__ __launch_bounds__(256) void split_k(const float* __restrict__ in,
                                               __nv_bfloat16* __restrict__ hi,
                                               __nv_bfloat16* __restrict__ lo, int n4)
{
    int idx = blockIdx.x * 256 + threadIdx.x;
    if (idx >= n4) return;
    float4 v = ((const float4*)in)[idx];
    __nv_bfloat16 h0 = __float2bfloat16(v.x), h1 = __float2bfloat16(v.y);
    __nv_bfloat16 h2 = __float2bfloat16(v.z), h3 = __float2bfloat16(v.w);
    __nv_bfloat16 l0 = __float2bfloat16(v.x - __bfloat162float(h0));
    __nv_bfloat16 l1 = __float2bfloat16(v.y - __bfloat162float(h1));
    __nv_bfloat16 l2 = __float2bfloat16(v.z - __bfloat162float(h2));
    __nv_bfloat16 l3 = __float2bfloat16(v.w - __bfloat162float(h3));
    ((__nv_bfloat162*)hi)[idx * 2]     = __nv_bfloat162(h0, h1);
    ((__nv_bfloat162*)hi)[idx * 2 + 1] = __nv_bfloat162(h2, h3);
    ((__nv_bfloat162*)lo)[idx * 2]     = __nv_bfloat162(l0, l1);
    ((__nv_bfloat162*)lo)[idx * 2 + 1] = __nv_bfloat162(l2, l3);
}

// ---------------------------------------------------------------------------
// W[K][N] -> Wt[N][K] bf16 hi/lo split (tiled transpose)
// ---------------------------------------------------------------------------
__global__ __launch_bounds__(256) void tsplit_k(const float* __restrict__ W,
                                                __nv_bfloat16* __restrict__ hi,
                                                __nv_bfloat16* __restrict__ lo,
                                                int K, int N)
{
    __shared__ float t[32][33];
    const int n0 = blockIdx.x * 32, k0 = blockIdx.y * 32;
    const int txi = threadIdx.x, tyi = threadIdx.y;
#pragma unroll
    for (int i = 0; i < 4; i++)
        t[tyi + i * 8][txi] = W[(size_t)(k0 + tyi + i * 8) * N + n0 + txi];
    __syncthreads();
#pragma unroll
    for (int i = 0; i < 4; i++) {
        float v = t[txi][tyi + i * 8];
        __nv_bfloat16 h = __float2bfloat16(v);
        __nv_bfloat16 l = __float2bfloat16(v - __bfloat162float(h));
        size_t o = (size_t)(n0 + tyi + i * 8) * K + k0 + txi;
        hi[o] = h;
        lo[o] = l;
    }
}

// ---------------------------------------------------------------------------
// mma.sync split-bf16 GEMM: C[M,N] = A[M,K] @ Bt[N,K]^T + bias[N]
// CTA 128x128, BK=64, 8 warps (4m x 2n), warp tile 32x64.
// D = Ah*Bh + Al*Bh + Ah*Bl accumulated in fp32 (ll term dropped, ~2^-16).
// smem rows padded to 144B so ldmatrix row addresses land on distinct banks.
// ---------------------------------------------------------------------------
#define GBM 128
#define GBN 128
#define GBK 64
#define LROW 144
#define TILE_B (128 * LROW)      // 18432
#define GEMM_SMEM (4 * TILE_B)   // 73728

__global__ __launch_bounds__(256) void gemm_mma(
    const __nv_bfloat16* __restrict__ Ah, const __nv_bfloat16* __restrict__ Al,
    const __nv_bfloat16* __restrict__ Bh, const __nv_bfloat16* __restrict__ Bl,
    const float* __restrict__ bias, float* __restrict__ C,
    int M, int N, int K)
{
    extern __shared__ __align__(128) char sm[];
    char* sAh = sm;
    char* sAl = sm + TILE_B;
    char* sBh = sm + 2 * TILE_B;
    char* sBl = sm + 3 * TILE_B;
    const uint32_t sb = smem_u32(sm);
    const int tid = threadIdx.x;
    const int wid = tid >> 5, lane = tid & 31;
    const int wm = wid & 3, wn = wid >> 2;
    const int bm = blockIdx.y * GBM, bn = blockIdx.x * GBN;

    float acc[2][8][4];
#pragma unroll
    for (int mi = 0; mi < 2; mi++)
#pragma unroll
        for (int ni = 0; ni < 8; ni++)
#pragma unroll
            for (int c = 0; c < 4; c++) acc[mi][ni][c] = 0.f;

    // ldmatrix per-lane addressing
    const uint32_t aRow = (uint32_t)(wm * 32 + (lane & 15));
    const uint32_t aKb  = (uint32_t)((lane >> 4) * 16);
    const uint32_t bRow = (uint32_t)(wn * 64 + (lane & 7) + ((lane >> 4) << 3));
    const uint32_t bKb  = (uint32_t)(((lane >> 3) & 1) * 16);

    for (int k0 = 0; k0 < K; k0 += GBK) {
        // fill: 128 rows x 64 bf16 per tile, 4 tiles
#pragma unroll
        for (int it = 0; it < 4; it++) {
            int idx = tid + it * 256;
            int r = idx >> 3, c8 = idx & 7;
            size_t ga = (size_t)(bm + r) * K + k0 + c8 * 8;
            size_t gb = (size_t)(bn + r) * K + k0 + c8 * 8;
            int so = r * LROW + c8 * 16;
            *(uint4*)(sAh + so) = *(const uint4*)(Ah + ga);
            *(uint4*)(sAl + so) = *(const uint4*)(Al + ga);
            *(uint4*)(sBh + so) = *(const uint4*)(Bh + gb);
            *(uint4*)(sBl + so) = *(const uint4*)(Bl + gb);
        }
        __syncthreads();

#pragma unroll
        for (int ks = 0; ks < 4; ks++) {
            uint32_t ah[2][4], al[2][4];
#pragma unroll
            for (int mi = 0; mi < 2; mi++) {
                uint32_t ad = sb + (aRow + mi * 16) * LROW + ks * 32 + aKb;
                LDSM_X4(ah[mi][0], ah[mi][1], ah[mi][2], ah[mi][3], ad);
                LDSM_X4(al[mi][0], al[mi][1], al[mi][2], al[mi][3], ad + TILE_B);
            }
#pragma unroll
            for (int np = 0; np < 4; np++) {
                uint32_t bd = sb + 2 * TILE_B + (bRow + np * 16) * LROW + ks * 32 + bKb;
                uint32_t bh0, bh1, bh2, bh3, bl0, bl1, bl2, bl3;
                LDSM_X4(bh0, bh1, bh2, bh3, bd);
                LDSM_X4(bl0, bl1, bl2, bl3, bd + TILE_B);
#pragma unroll
                for (int mi = 0; mi < 2; mi++) {
                    float* d0 = acc[mi][np * 2];
                    float* d1 = acc[mi][np * 2 + 1];
                    MMA_BF16(d0, ah[mi][0], ah[mi][1], ah[mi][2], ah[mi][3], bh0, bh1);
                    MMA_BF16(d0, al[mi][0], al[mi][1], al[mi][2], al[mi][3], bh0, bh1);
                    MMA_BF16(d0, ah[mi][0], ah[mi][1], ah[mi][2], ah[mi][3], bl0, bl1);
                    MMA_BF16(d1, ah[mi][0], ah[mi][1], ah[mi][2], ah[mi][3], bh2, bh3);
                    MMA_BF16(d1, al[mi][0], al[mi][1], al[mi][2], al[mi][3], bh2, bh3);
                    MMA_BF16(d1, ah[mi][0], ah[mi][1], ah[mi][2], ah[mi][3], bl2, bl3);
                }
            }
        }
        __syncthreads();
    }

    // epilogue: accum frag (thread lane) -> C + bias
    const int gr = lane >> 2, qc = lane & 3;
#pragma unroll
    for (int mi = 0; mi < 2; mi++) {
#pragma unroll
        for (int ni = 0; ni < 8; ni++) {
            int row0 = bm + wm * 32 + mi * 16 + gr;
            int col = bn + wn * 64 + ni * 8 + qc * 2;
            float b0 = bias[col], b1 = bias[col + 1];
            float2 v0, v1;
            v0.x = acc[mi][ni][0] + b0;
            v0.y = acc[mi][ni][1] + b1;
            v1.x = acc[mi][ni][2] + b0;
            v1.y = acc[mi][ni][3] + b1;
            *(float2*)(C + (size_t)row0 * N + col) = v0;
            *(float2*)(C + (size_t)(row0 + 8) * N + col) = v1;
        }
    }
}

// ---------------------------------------------------------------------------
// Flash-style fp32 attention (unchanged from passing R1 kernel)
// ---------------------------------------------------------------------------
__global__ __launch_bounds__(256) void attn_k(const float* __restrict__ qkv,
                                              float* __restrict__ y)
{
    extern __shared__ float smf[];
    float* Qs = smf;
    float* Ks = Qs + 64 * 65;
    float* Ps = Ks + 64 * 65;
    float* Vs = Ps + 64 * 65;

    const int tid = threadIdx.x;
    const int tx = tid & 15, ty = tid >> 4;
    const int q0 = blockIdx.x * 64;
    const int h = blockIdx.y;
    const int b = blockIdx.z;
    const size_t base = (size_t)b * T_ * QKVC;
    const int qoff = h * HD_;
    const int koff = C_ + h * HD_;
    const int voff = 2 * C_ + h * HD_;

    for (int i = tid; i < 64 * 16; i += 256) {
        int r = i >> 4, cv = (i & 15) << 2;
        float4 v = *(const float4*)(qkv + base + (size_t)(q0 + r) * QKVC + qoff + cv);
        Qs[r * 65 + cv + 0] = v.x * 0.125f;
        Qs[r * 65 + cv + 1] = v.y * 0.125f;
        Qs[r * 65 + cv + 2] = v.z * 0.125f;
        Qs[r * 65 + cv + 3] = v.w * 0.125f;
    }

    float m_run[4], l_run[4], o[4][4];
#pragma unroll
    for (int i = 0; i < 4; i++) {
        m_run[i] = -1e30f;
        l_run[i] = 0.f;
#pragma unroll
        for (int j = 0; j < 4; j++) o[i][j] = 0.f;
    }

    for (int t0 = 0; t0 < T_; t0 += 64) {
        __syncthreads();
        for (int i = tid; i < 64 * 16; i += 256) {
            int r = i >> 4, cv = (i & 15) << 2;
            const float* rowp = qkv + base + (size_t)(t0 + r) * QKVC;
            float4 kv = *(const float4*)(rowp + koff + cv);
            Ks[r * 65 + cv + 0] = kv.x;
            Ks[r * 65 + cv + 1] = kv.y;
            Ks[r * 65 + cv + 2] = kv.z;
            Ks[r * 65 + cv + 3] = kv.w;
            *(float4*)(Vs + r * 64 + cv) = *(const float4*)(rowp + voff + cv);
        }
        __syncthreads();

        float s[4][4];
#pragma unroll
        for (int i = 0; i < 4; i++)
#pragma unroll
            for (int j = 0; j < 4; j++) s[i][j] = 0.f;

#pragma unroll 16
        for (int kk = 0; kk < 64; kk++) {
            float a[4], bb[4];
#pragma unroll
            for (int i = 0; i < 4; i++) a[i] = Qs[(ty * 4 + i) * 65 + kk];
#pragma unroll
            for (int j = 0; j < 4; j++) bb[j] = Ks[(tx * 4 + j) * 65 + kk];
#pragma unroll
            for (int i = 0; i < 4; i++)
#pragma unroll
                for (int j = 0; j < 4; j++)
                    s[i][j] = fmaf(a[i], bb[j], s[i][j]);
        }

        float mt[4];
#pragma unroll
        for (int i = 0; i < 4; i++)
            mt[i] = fmaxf(fmaxf(s[i][0], s[i][1]), fmaxf(s[i][2], s[i][3]));
#pragma unroll
        for (int off = 8; off > 0; off >>= 1)
#pragma unroll
            for (int i = 0; i < 4; i++)
                mt[i] = fmaxf(mt[i], __shfl_xor_sync(0xffffffffu, mt[i], off));

        float alpha[4], lt[4];
#pragma unroll
        for (int i = 0; i < 4; i++) {
            float mn = fmaxf(m_run[i], mt[i]);
            alpha[i] = __expf(m_run[i] - mn);
            m_run[i] = mn;
            lt[i] = 0.f;
#pragma unroll
            for (int j = 0; j < 4; j++) {
                float p = __expf(s[i][j] - mn);
                s[i][j] = p;
                lt[i] += p;
            }
        }
#pragma unroll
        for (int off = 8; off > 0; off >>= 1)
#pragma unroll
            for (int i = 0; i < 4; i++)
                lt[i] += __shfl_xor_sync(0xffffffffu, lt[i], off);
#pragma unroll
        for (int i = 0; i < 4; i++) l_run[i] = l_run[i] * alpha[i] + lt[i];

#pragma unroll
        for (int i = 0; i < 4; i++)
#pragma unroll
            for (int j = 0; j < 4; j++) {
                Ps[(ty * 4 + i) * 65 + tx * 4 + j] = s[i][j];
                o[i][j] *= alpha[i];
            }
        __syncthreads();

#pragma unroll 16
        for (int kk = 0; kk < 64; kk++) {
            float4 bv = *(const float4*)(Vs + kk * 64 + tx * 4);
#pragma unroll
            for (int i = 0; i < 4; i++) {
                float a = Ps[(ty * 4 + i) * 65 + kk];
                o[i][0] = fmaf(a, bv.x, o[i][0]);
                o[i][1] = fmaf(a, bv.y, o[i][1]);
                o[i][2] = fmaf(a, bv.z, o[i][2]);
                o[i][3] = fmaf(a, bv.w, o[i][3]);
            }
        }
    }

#pragma unroll
    for (int i = 0; i < 4; i++) {
        float inv = 1.f / l_run[i];
        float4 ov;
        ov.x = o[i][0] * inv;
        ov.y = o[i][1] * inv;
        ov.z = o[i][2] * inv;
        ov.w = o[i][3] * inv;
        *(float4*)(y + (size_t)(b * T_ + q0 + ty * 4 + i) * C_ + h * HD_ + tx * 4) = ov;
    }
}

static const int ATTN_SMEM = (3 * 64 * 65 + 64 * 64) * (int)sizeof(float);

extern "C" void kernel_launch(void* const* d_in, const int* in_sizes, int n_in,
                              void* d_out, int out_size)
{
    (void)in_sizes; (void)n_in; (void)out_size;
    const float* x      = (const float*)d_in[0];
    const float* W_attn = (const float*)d_in[1];
    const float* b_attn = (const float*)d_in[2];
    const float* W_proj = (const float*)d_in[3];
    const float* b_proj = (const float*)d_in[4];
    float* out = (float*)d_out;

    float *qkv = nullptr, *yb = nullptr;
    __nv_bfloat16 *xh, *xl, *wah, *wal, *wph, *wpl;
    cudaGetSymbolAddress((void**)&qkv, g_qkv);
    cudaGetSymbolAddress((void**)&yb, g_y);
    cudaGetSymbolAddress((void**)&xh, g_xh);
    cudaGetSymbolAddress((void**)&xl, g_xl);
    cudaGetSymbolAddress((void**)&wah, g_wah);
    cudaGetSymbolAddress((void**)&wal, g_wal);
    cudaGetSymbolAddress((void**)&wph, g_wph);
    cudaGetSymbolAddress((void**)&wpl, g_wpl);

    cudaFuncSetAttribute(attn_k, cudaFuncAttributeMaxDynamicSharedMemorySize, ATTN_SMEM);
    cudaFuncSetAttribute(gemm_mma, cudaFuncAttributeMaxDynamicSharedMemorySize, GEMM_SMEM);

    const int n4x = (BT * C_) / 4;

    // split inputs to bf16 hi/lo (weights transposed to [N][K])
    split_k<<<(n4x + 255) / 256, 256>>>(x, xh, xl, n4x);
    tsplit_k<<<dim3(QKVC / 32, C_ / 32), dim3(32, 8)>>>(W_attn, wah, wal, C_, QKVC);
    tsplit_k<<<dim3(C_ / 32, C_ / 32), dim3(32, 8)>>>(W_proj, wph, wpl, C_, C_);

    // 1) qkv = x @ W_attn + b_attn  (mma.sync bf16-split)
    gemm_mma<<<dim3(QKVC / GBN, BT / GBM), 256, GEMM_SMEM>>>(
        xh, xl, wah, wal, b_attn, qkv, BT, QKVC, C_);

    // 2) y = SDPA(q,k,v)  (fp32)
    attn_k<<<dim3(T_ / 64, H_, B_), 256, ATTN_SMEM>>>(qkv, yb);

    // 3) out = y @ W_proj + b_proj  (mma.sync bf16-split); reuse xh/xl for y
    split_k<<<(n4x + 255) / 256, 256>>>(yb, xh, xl, n4x);
    gemm_mma<<<dim3(C_ / GBN, BT / GBM), 256, GEMM_SMEM>>>(
        xh, xl, wph, wpl, b_proj, out, BT, C_, C_);
}

// round 11
// speedup vs baseline: 3.0048x; 3.0048x over previous
#include <cuda_runtime.h>
#include <cuda_bf16.h>
#include <cstdint>

#define B_ 4
#define T_ 2048
#define C_ 1024
#define H_ 16
#define HD_ 64
#define QKVC (3 * C_)
#define BT (B_ * T_)

// ---------------- scratch (no cudaMalloc allowed) ----------------
__device__ float g_qkv[(size_t)BT * QKVC];                 // 96 MB fp32
__device__ float g_y[(size_t)BT * C_];                     // 32 MB fp32
__device__ __nv_bfloat16 g_xh[(size_t)BT * C_];
__device__ __nv_bfloat16 g_xl[(size_t)BT * C_];
__device__ __nv_bfloat16 g_wah[(size_t)QKVC * C_];
__device__ __nv_bfloat16 g_wal[(size_t)QKVC * C_];
__device__ __nv_bfloat16 g_wph[(size_t)C_ * C_];
__device__ __nv_bfloat16 g_wpl[(size_t)C_ * C_];

__device__ __forceinline__ uint32_t smem_u32(const void* p) {
    return (uint32_t)__cvta_generic_to_shared(p);
}

// ---- warp-level tensor core ops (sm_80-era PTX, legal on plain sm_103) ----
#define LDSM_X4(r0, r1, r2, r3, addr) \
    asm volatile("ldmatrix.sync.aligned.m8n8.x4.shared.b16 {%0,%1,%2,%3}, [%4];" \
        : "=r"(r0), "=r"(r1), "=r"(r2), "=r"(r3) : "r"(addr))

#define MMA_BF16(D, a0, a1, a2, a3, b0, b1) \
    asm volatile("mma.sync.aligned.m16n8k16.row.col.f32.bf16.bf16.f32 " \
        "{%0,%1,%2,%3}, {%4,%5,%6,%7}, {%8,%9}, {%0,%1,%2,%3};" \
        : "+f"((D)[0]), "+f"((D)[1]), "+f"((D)[2]), "+f"((D)[3]) \
        : "r"(a0), "r"(a1), "r"(a2), "r"(a3), "r"(b0), "r"(b1))

#define MMA_TF32(D, a0, a1, a2, a3, b0, b1) \
    asm volatile("mma.sync.aligned.m16n8k8.row.col.f32.tf32.tf32.f32 " \
        "{%0,%1,%2,%3}, {%4,%5,%6,%7}, {%8,%9}, {%0,%1,%2,%3};" \
        : "+f"((D)[0]), "+f"((D)[1]), "+f"((D)[2]), "+f"((D)[3]) \
        : "r"(a0), "r"(a1), "r"(a2), "r"(a3), "r"(b0), "r"(b1))

#define CP_ASYNC16(saddr, gptr) \
    asm volatile("cp.async.cg.shared.global [%0], [%1], 16;" \
        :: "r"(saddr), "l"(gptr))
#define CP_COMMIT() asm volatile("cp.async.commit_group;")
#define CP_WAIT(n)  asm volatile("cp.async.wait_group %0;" :: "n"(n))

__device__ __forceinline__ uint32_t f2tf32(float x) {
    uint32_t u;
    asm("cvt.rna.tf32.f32 %0, %1;" : "=r"(u) : "f"(x));
    return u;
}

// ---------------------------------------------------------------------------
// fp32 -> bf16 hi/lo split (elementwise)
// ---------------------------------------------------------------------------
__global__ __launch_bounds__(256) void split_k(const float* __restrict__ in,
                                               __nv_bfloat16* __restrict__ hi,
                                               __nv_bfloat16* __restrict__ lo, int n4)
{
    int idx = blockIdx.x * 256 + threadIdx.x;
    if (idx >= n4) return;
    float4 v = ((const float4*)in)[idx];
    __nv_bfloat16 h0 = __float2bfloat16(v.x), h1 = __float2bfloat16(v.y);
    __nv_bfloat16 h2 = __float2bfloat16(v.z), h3 = __float2bfloat16(v.w);
    __nv_bfloat16 l0 = __float2bfloat16(v.x - __bfloat162float(h0));
    __nv_bfloat16 l1 = __float2bfloat16(v.y - __bfloat162float(h1));
    __nv_bfloat16 l2 = __float2bfloat16(v.z - __bfloat162float(h2));
    __nv_bfloat16 l3 = __float2bfloat16(v.w - __bfloat162float(h3));
    ((__nv_bfloat162*)hi)[idx * 2]     = __nv_bfloat162(h0, h1);
    ((__nv_bfloat162*)hi)[idx * 2 + 1] = __nv_bfloat162(h2, h3);
    ((__nv_bfloat162*)lo)[idx * 2]     = __nv_bfloat162(l0, l1);
    ((__nv_bfloat162*)lo)[idx * 2 + 1] = __nv_bfloat162(l2, l3);
}

// ---------------------------------------------------------------------------
// W[K][N] -> Wt[N][K] bf16 hi/lo split (tiled transpose)
// ---------------------------------------------------------------------------
__global__ __launch_bounds__(256) void tsplit_k(const float* __restrict__ W,
                                                __nv_bfloat16* __restrict__ hi,
                                                __nv_bfloat16* __restrict__ lo,
                                                int K, int N)
{
    __shared__ float t[32][33];
    const int n0 = blockIdx.x * 32, k0 = blockIdx.y * 32;
    const int txi = threadIdx.x, tyi = threadIdx.y;
#pragma unroll
    for (int i = 0; i < 4; i++)
        t[tyi + i * 8][txi] = W[(size_t)(k0 + tyi + i * 8) * N + n0 + txi];
    __syncthreads();
#pragma unroll
    for (int i = 0; i < 4; i++) {
        float v = t[txi][tyi + i * 8];
        __nv_bfloat16 h = __float2bfloat16(v);
        __nv_bfloat16 l = __float2bfloat16(v - __bfloat162float(h));
        size_t o = (size_t)(n0 + tyi + i * 8) * K + k0 + txi;
        hi[o] = h;
        lo[o] = l;
    }
}

// ---------------------------------------------------------------------------
// mma.sync split-bf16 GEMM with 2-stage cp.async pipeline.
// C[M,N] = A[M,K] @ Bt[N,K]^T + bias[N]. CTA 128x128, BK=64, 8 warps.
// ---------------------------------------------------------------------------
#define GBM 128
#define GBN 128
#define GBK 64
#define LROW 144
#define TILE_B (128 * LROW)        // 18432
#define STG_B  (4 * TILE_B)        // 73728 per stage
#define GEMM_SMEM (2 * STG_B)      // 147456

__global__ __launch_bounds__(256) void gemm_mma(
    const __nv_bfloat16* __restrict__ Ah, const __nv_bfloat16* __restrict__ Al,
    const __nv_bfloat16* __restrict__ Bh, const __nv_bfloat16* __restrict__ Bl,
    const float* __restrict__ bias, float* __restrict__ C,
    int M, int N, int K)
{
    extern __shared__ __align__(128) char sm[];
    const uint32_t sb = smem_u32(sm);
    const int tid = threadIdx.x;
    const int wid = tid >> 5, lane = tid & 31;
    const int wm = wid & 3, wn = wid >> 2;
    const int bm = blockIdx.y * GBM, bn = blockIdx.x * GBN;

    float acc[2][8][4];
#pragma unroll
    for (int mi = 0; mi < 2; mi++)
#pragma unroll
        for (int ni = 0; ni < 8; ni++)
#pragma unroll
            for (int c = 0; c < 4; c++) acc[mi][ni][c] = 0.f;

    const uint32_t aRow = (uint32_t)(wm * 32 + (lane & 15));
    const uint32_t aKb  = (uint32_t)((lane >> 4) * 16);
    const uint32_t bRow = (uint32_t)(wn * 64 + (lane & 7) + ((lane >> 4) << 3));
    const uint32_t bKb  = (uint32_t)(((lane >> 3) & 1) * 16);

    // per-thread load geometry (8 rows x 8 col-chunks per 256 threads x 4 iters)
    const int KT = K / GBK;

#define LOAD_STAGE(s, k0)                                                      \
    do {                                                                       \
        uint32_t sbase = sb + (uint32_t)(s) * STG_B;                           \
        _Pragma("unroll")                                                      \
        for (int it = 0; it < 4; it++) {                                       \
            int idx = tid + it * 256;                                          \
            int r = idx >> 3, c8 = idx & 7;                                    \
            uint32_t so = (uint32_t)(r * LROW + c8 * 16);                      \
            const __nv_bfloat16* pa = Ah + (size_t)(bm + r) * K + (k0) + c8 * 8; \
            const __nv_bfloat16* pl = Al + (size_t)(bm + r) * K + (k0) + c8 * 8; \
            const __nv_bfloat16* pb = Bh + (size_t)(bn + r) * K + (k0) + c8 * 8; \
            const __nv_bfloat16* pc = Bl + (size_t)(bn + r) * K + (k0) + c8 * 8; \
            CP_ASYNC16(sbase + so, pa);                                        \
            CP_ASYNC16(sbase + TILE_B + so, pl);                               \
            CP_ASYNC16(sbase + 2 * TILE_B + so, pb);                           \
            CP_ASYNC16(sbase + 3 * TILE_B + so, pc);                           \
        }                                                                      \
    } while (0)

    LOAD_STAGE(0, 0);
    CP_COMMIT();

    for (int kt = 0; kt < KT; kt++) {
        if (kt + 1 < KT) {
            LOAD_STAGE((kt + 1) & 1, (kt + 1) * GBK);
            CP_COMMIT();
            CP_WAIT(1);
        } else {
            CP_WAIT(0);
        }
        __syncthreads();

        const uint32_t stg = sb + (uint32_t)(kt & 1) * STG_B;
#pragma unroll
        for (int ks = 0; ks < 4; ks++) {
            uint32_t ah[2][4], al[2][4];
#pragma unroll
            for (int mi = 0; mi < 2; mi++) {
                uint32_t ad = stg + (aRow + mi * 16) * LROW + ks * 32 + aKb;
                LDSM_X4(ah[mi][0], ah[mi][1], ah[mi][2], ah[mi][3], ad);
                LDSM_X4(al[mi][0], al[mi][1], al[mi][2], al[mi][3], ad + TILE_B);
            }
#pragma unroll
            for (int np = 0; np < 4; np++) {
                uint32_t bd = stg + 2 * TILE_B + (bRow + np * 16) * LROW + ks * 32 + bKb;
                uint32_t bh0, bh1, bh2, bh3, bl0, bl1, bl2, bl3;
                LDSM_X4(bh0, bh1, bh2, bh3, bd);
                LDSM_X4(bl0, bl1, bl2, bl3, bd + TILE_B);
#pragma unroll
                for (int mi = 0; mi < 2; mi++) {
                    float* d0 = acc[mi][np * 2];
                    float* d1 = acc[mi][np * 2 + 1];
                    MMA_BF16(d0, ah[mi][0], ah[mi][1], ah[mi][2], ah[mi][3], bh0, bh1);
                    MMA_BF16(d0, al[mi][0], al[mi][1], al[mi][2], al[mi][3], bh0, bh1);
                    MMA_BF16(d0, ah[mi][0], ah[mi][1], ah[mi][2], ah[mi][3], bl0, bl1);
                    MMA_BF16(d1, ah[mi][0], ah[mi][1], ah[mi][2], ah[mi][3], bh2, bh3);
                    MMA_BF16(d1, al[mi][0], al[mi][1], al[mi][2], al[mi][3], bh2, bh3);
                    MMA_BF16(d1, ah[mi][0], ah[mi][1], ah[mi][2], ah[mi][3], bl2, bl3);
                }
            }
        }
        __syncthreads();
    }

    const int gr = lane >> 2, qc = lane & 3;
#pragma unroll
    for (int mi = 0; mi < 2; mi++) {
#pragma unroll
        for (int ni = 0; ni < 8; ni++) {
            int row0 = bm + wm * 32 + mi * 16 + gr;
            int col = bn + wn * 64 + ni * 8 + qc * 2;
            float b0 = bias[col], b1 = bias[col + 1];
            float2 v0, v1;
            v0.x = acc[mi][ni][0] + b0;
            v0.y = acc[mi][ni][1] + b1;
            v1.x = acc[mi][ni][2] + b0;
            v1.y = acc[mi][ni][3] + b1;
            *(float2*)(C + (size_t)row0 * N + col) = v0;
            *(float2*)(C + (size_t)(row0 + 8) * N + col) = v1;
        }
    }
}

// ---------------------------------------------------------------------------
// Flash attention with tf32 mma.sync. Grid (T/64, H, B), 128 threads (4 warps).
// Warp w owns rows 16w..16w+15 of the 64-query tile, full 64-key width ->
// softmax stays warp-local. smem rows padded to 72 floats: every fragment
// LDS/STS pattern maps lanes to 32 distinct banks.
// ---------------------------------------------------------------------------
#define AT_PAD 72
#define ATTN_SMEM (4 * 64 * AT_PAD * 4)   // Qs,Ks,Vs,Ps = 73728 B

__global__ __launch_bounds__(128) void attn_mma(const float* __restrict__ qkv,
                                                float* __restrict__ y)
{
    extern __shared__ __align__(128) float smf[];
    uint32_t* Qs = (uint32_t*)smf;
    uint32_t* Ks = Qs + 64 * AT_PAD;
    uint32_t* Vs = Ks + 64 * AT_PAD;
    uint32_t* Ps = Vs + 64 * AT_PAD;

    const int tid = threadIdx.x;
    const int w = tid >> 5, lane = tid & 31;
    const int g = lane >> 2, q = lane & 3;
    const int q0 = blockIdx.x * 64;
    const int h = blockIdx.y;
    const int b = blockIdx.z;
    const size_t base = (size_t)b * T_ * QKVC;
    const int qoff = h * HD_;
    const int koff = C_ + h * HD_;
    const int voff = 2 * C_ + h * HD_;

    // load Q tile (scaled by 1/8, tf32-rounded)
    for (int i = tid; i < 64 * 16; i += 128) {
        int r = i >> 4, c4 = (i & 15) << 2;
        float4 v = *(const float4*)(qkv + base + (size_t)(q0 + r) * QKVC + qoff + c4);
        Qs[r * AT_PAD + c4 + 0] = f2tf32(v.x * 0.125f);
        Qs[r * AT_PAD + c4 + 1] = f2tf32(v.y * 0.125f);
        Qs[r * AT_PAD + c4 + 2] = f2tf32(v.z * 0.125f);
        Qs[r * AT_PAD + c4 + 3] = f2tf32(v.w * 0.125f);
    }

    float m0 = -1e30f, m1 = -1e30f, l0 = 0.f, l1 = 0.f;
    float o[8][4];
#pragma unroll
    for (int nt = 0; nt < 8; nt++)
#pragma unroll
        for (int c = 0; c < 4; c++) o[nt][c] = 0.f;

    const int rA0 = (16 * w + g) * AT_PAD;       // warp's row g
    const int rA1 = (16 * w + g + 8) * AT_PAD;   // warp's row g+8

    for (int t0 = 0; t0 < T_; t0 += 64) {
        __syncthreads();   // prev tile's K/V reads done (also orders Q load, iter 0)
        for (int i = tid; i < 64 * 16; i += 128) {
            int r = i >> 4, c4 = (i & 15) << 2;
            const float* rowp = qkv + base + (size_t)(t0 + r) * QKVC;
            float4 kv = *(const float4*)(rowp + koff + c4);
            float4 vv = *(const float4*)(rowp + voff + c4);
            Ks[r * AT_PAD + c4 + 0] = f2tf32(kv.x);
            Ks[r * AT_PAD + c4 + 1] = f2tf32(kv.y);
            Ks[r * AT_PAD + c4 + 2] = f2tf32(kv.z);
            Ks[r * AT_PAD + c4 + 3] = f2tf32(kv.w);
            Vs[r * AT_PAD + c4 + 0] = f2tf32(vv.x);
            Vs[r * AT_PAD + c4 + 1] = f2tf32(vv.y);
            Vs[r * AT_PAD + c4 + 2] = f2tf32(vv.z);
            Vs[r * AT_PAD + c4 + 3] = f2tf32(vv.w);
        }
        __syncthreads();

        // S = Q K^T : warp rows 16w..16w+15, cols 0..63
        float s[8][4];
#pragma unroll
        for (int nt = 0; nt < 8; nt++)
#pragma unroll
            for (int c = 0; c < 4; c++) s[nt][c] = 0.f;

#pragma unroll
        for (int kt = 0; kt < 8; kt++) {
            uint32_t a0 = Qs[rA0 + q + 8 * kt];
            uint32_t a1 = Qs[rA1 + q + 8 * kt];
            uint32_t a2 = Qs[rA0 + q + 4 + 8 * kt];
            uint32_t a3 = Qs[rA1 + q + 4 + 8 * kt];
#pragma unroll
            for (int nt = 0; nt < 8; nt++) {
                uint32_t b0 = Ks[(nt * 8 + g) * AT_PAD + q + 8 * kt];
                uint32_t b1 = Ks[(nt * 8 + g) * AT_PAD + q + 4 + 8 * kt];
                MMA_TF32(s[nt], a0, a1, a2, a3, b0, b1);
            }
        }

        // online softmax (rows g and g+8, warp-local: lanes 4g..4g+3)
        float mt0 = -1e30f, mt1 = -1e30f;
#pragma unroll
        for (int nt = 0; nt < 8; nt++) {
            mt0 = fmaxf(mt0, fmaxf(s[nt][0], s[nt][1]));
            mt1 = fmaxf(mt1, fmaxf(s[nt][2], s[nt][3]));
        }
#pragma unroll
        for (int off = 1; off <= 2; off <<= 1) {
            mt0 = fmaxf(mt0, __shfl_xor_sync(0xffffffffu, mt0, off));
            mt1 = fmaxf(mt1, __shfl_xor_sync(0xffffffffu, mt1, off));
        }
        float mn0 = fmaxf(m0, mt0), mn1 = fmaxf(m1, mt1);
        float al0 = __expf(m0 - mn0), al1 = __expf(m1 - mn1);
        m0 = mn0;
        m1 = mn1;

        float lt0 = 0.f, lt1 = 0.f;
#pragma unroll
        for (int nt = 0; nt < 8; nt++) {
            float p0 = __expf(s[nt][0] - mn0);
            float p1 = __expf(s[nt][1] - mn0);
            float p2 = __expf(s[nt][2] - mn1);
            float p3 = __expf(s[nt][3] - mn1);
            lt0 += p0 + p1;
            lt1 += p2 + p3;
            Ps[rA0 + nt * 8 + 2 * q]     = f2tf32(p0);
            Ps[rA0 + nt * 8 + 2 * q + 1] = f2tf32(p1);
            Ps[rA1 + nt * 8 + 2 * q]     = f2tf32(p2);
            Ps[rA1 + nt * 8 + 2 * q + 1] = f2tf32(p3);
        }
#pragma unroll
        for (int off = 1; off <= 2; off <<= 1) {
            lt0 += __shfl_xor_sync(0xffffffffu, lt0, off);
            lt1 += __shfl_xor_sync(0xffffffffu, lt1, off);
        }
        l0 = l0 * al0 + lt0;
        l1 = l1 * al1 + lt1;

#pragma unroll
        for (int nt = 0; nt < 8; nt++) {
            o[nt][0] *= al0;
            o[nt][1] *= al0;
            o[nt][2] *= al1;
            o[nt][3] *= al1;
        }
        __syncwarp();   // P written/read by this warp only

        // O += P V : A = P (warp rows, k = key), B = V[k][d]
#pragma unroll
        for (int kt = 0; kt < 8; kt++) {
            uint32_t a0 = Ps[rA0 + q + 8 * kt];
            uint32_t a1 = Ps[rA1 + q + 8 * kt];
            uint32_t a2 = Ps[rA0 + q + 4 + 8 * kt];
            uint32_t a3 = Ps[rA1 + q + 4 + 8 * kt];
#pragma unroll
            for (int nt = 0; nt < 8; nt++) {
                uint32_t b0 = Vs[(8 * kt + q) * AT_PAD + nt * 8 + g];
                uint32_t b1 = Vs[(8 * kt + q + 4) * AT_PAD + nt * 8 + g];
                MMA_TF32(o[nt], a0, a1, a2, a3, b0, b1);
            }
        }
    }

    // normalize + store
    const float inv0 = 1.f / l0, inv1 = 1.f / l1;
    const int r0 = b * T_ + q0 + 16 * w + g;
#pragma unroll
    for (int nt = 0; nt < 8; nt++) {
        float2 v0, v1;
        v0.x = o[nt][0] * inv0;
        v0.y = o[nt][1] * inv0;
        v1.x = o[nt][2] * inv1;
        v1.y = o[nt][3] * inv1;
        *(float2*)(y + (size_t)r0 * C_ + h * HD_ + nt * 8 + 2 * q) = v0;
        *(float2*)(y + (size_t)(r0 + 8) * C_ + h * HD_ + nt * 8 + 2 * q) = v1;
    }
}

extern "C" void kernel_launch(void* const* d_in, const int* in_sizes, int n_in,
                              void* d_out, int out_size)
{
    (void)in_sizes; (void)n_in; (void)out_size;
    const float* x      = (const float*)d_in[0];
    const float* W_attn = (const float*)d_in[1];
    const float* b_attn = (const float*)d_in[2];
    const float* W_proj = (const float*)d_in[3];
    const float* b_proj = (const float*)d_in[4];
    float* out = (float*)d_out;

    float *qkv = nullptr, *yb = nullptr;
    __nv_bfloat16 *xh, *xl, *wah, *wal, *wph, *wpl;
    cudaGetSymbolAddress((void**)&qkv, g_qkv);
    cudaGetSymbolAddress((void**)&yb, g_y);
    cudaGetSymbolAddress((void**)&xh, g_xh);
    cudaGetSymbolAddress((void**)&xl, g_xl);
    cudaGetSymbolAddress((void**)&wah, g_wah);
    cudaGetSymbolAddress((void**)&wal, g_wal);
    cudaGetSymbolAddress((void**)&wph, g_wph);
    cudaGetSymbolAddress((void**)&wpl, g_wpl);

    cudaFuncSetAttribute(attn_mma, cudaFuncAttributeMaxDynamicSharedMemorySize, ATTN_SMEM);
    cudaFuncSetAttribute(gemm_mma, cudaFuncAttributeMaxDynamicSharedMemorySize, GEMM_SMEM);

    const int n4x = (BT * C_) / 4;

    // split inputs to bf16 hi/lo (weights transposed to [N][K])
    split_k<<<(n4x + 255) / 256, 256>>>(x, xh, xl, n4x);
    tsplit_k<<<dim3(QKVC / 32, C_ / 32), dim3(32, 8)>>>(W_attn, wah, wal, C_, QKVC);
    tsplit_k<<<dim3(C_ / 32, C_ / 32), dim3(32, 8)>>>(W_proj, wph, wpl, C_, C_);

    // 1) qkv = x @ W_attn + b_attn  (bf16-split HMMA, cp.async pipelined)
    gemm_mma<<<dim3(QKVC / GBN, BT / GBM), 256, GEMM_SMEM>>>(
        xh, xl, wah, wal, b_attn, qkv, BT, QKVC, C_);

    // 2) y = SDPA(q,k,v)  (tf32 HMMA flash attention)
    attn_mma<<<dim3(T_ / 64, H_, B_), 128, ATTN_SMEM>>>(qkv, yb);

    // 3) out = y @ W_proj + b_proj  (bf16-split HMMA); reuse xh/xl for y
    split_k<<<(n4x + 255) / 256, 256>>>(yb, xh, xl, n4x);
    gemm_mma<<<dim3(C_ / GBN, BT / GBM), 256, GEMM_SMEM>>>(
        xh, xl, wph, wpl, b_proj, out, BT, C_, C_);
}

// round 12
// speedup vs baseline: 3.2246x; 1.0732x over previous
#include <cuda_runtime.h>
#include <cuda_bf16.h>
#include <cstdint>

#define B_ 4
#define T_ 2048
#define C_ 1024
#define H_ 16
#define HD_ 64
#define QKVC (3 * C_)
#define BT (B_ * T_)

// ---------------- scratch (no cudaMalloc allowed) ----------------
__device__ float g_qkv[(size_t)BT * QKVC];                 // 96 MB fp32
__device__ __nv_bfloat16 g_xh[(size_t)BT * C_];            // act split (x, then attn out)
__device__ __nv_bfloat16 g_xl[(size_t)BT * C_];
__device__ __nv_bfloat16 g_wah[(size_t)QKVC * C_];
__device__ __nv_bfloat16 g_wal[(size_t)QKVC * C_];
__device__ __nv_bfloat16 g_wph[(size_t)C_ * C_];
__device__ __nv_bfloat16 g_wpl[(size_t)C_ * C_];

__device__ __forceinline__ uint32_t smem_u32(const void* p) {
    return (uint32_t)__cvta_generic_to_shared(p);
}

// ---- warp-level tensor core ops (sm_80-era PTX, legal on plain sm_103) ----
#define LDSM_X4(r0, r1, r2, r3, addr) \
    asm volatile("ldmatrix.sync.aligned.m8n8.x4.shared.b16 {%0,%1,%2,%3}, [%4];" \
        : "=r"(r0), "=r"(r1), "=r"(r2), "=r"(r3) : "r"(addr))

#define MMA_BF16(D, a0, a1, a2, a3, b0, b1) \
    asm volatile("mma.sync.aligned.m16n8k16.row.col.f32.bf16.bf16.f32 " \
        "{%0,%1,%2,%3}, {%4,%5,%6,%7}, {%8,%9}, {%0,%1,%2,%3};" \
        : "+f"((D)[0]), "+f"((D)[1]), "+f"((D)[2]), "+f"((D)[3]) \
        : "r"(a0), "r"(a1), "r"(a2), "r"(a3), "r"(b0), "r"(b1))

#define MMA_TF32(D, a0, a1, a2, a3, b0, b1) \
    asm volatile("mma.sync.aligned.m16n8k8.row.col.f32.tf32.tf32.f32 " \
        "{%0,%1,%2,%3}, {%4,%5,%6,%7}, {%8,%9}, {%0,%1,%2,%3};" \
        : "+f"((D)[0]), "+f"((D)[1]), "+f"((D)[2]), "+f"((D)[3]) \
        : "r"(a0), "r"(a1), "r"(a2), "r"(a3), "r"(b0), "r"(b1))

#define CP_ASYNC16(saddr, gptr) \
    asm volatile("cp.async.cg.shared.global [%0], [%1], 16;" \
        :: "r"(saddr), "l"(gptr))
#define CP_COMMIT() asm volatile("cp.async.commit_group;")
#define CP_WAIT(n)  asm volatile("cp.async.wait_group %0;" :: "n"(n))

// ---------------------------------------------------------------------------
// fp32 -> bf16 hi/lo split (elementwise)
// ---------------------------------------------------------------------------
__global__ __launch_bounds__(256) void split_k(const float* __restrict__ in,
                                               __nv_bfloat16* __restrict__ hi,
                                               __nv_bfloat16* __restrict__ lo, int n4)
{
    int idx = blockIdx.x * 256 + threadIdx.x;
    if (idx >= n4) return;
    float4 v = ((const float4*)in)[idx];
    __nv_bfloat16 h0 = __float2bfloat16(v.x), h1 = __float2bfloat16(v.y);
    __nv_bfloat16 h2 = __float2bfloat16(v.z), h3 = __float2bfloat16(v.w);
    __nv_bfloat16 l0 = __float2bfloat16(v.x - __bfloat162float(h0));
    __nv_bfloat16 l1 = __float2bfloat16(v.y - __bfloat162float(h1));
    __nv_bfloat16 l2 = __float2bfloat16(v.z - __bfloat162float(h2));
    __nv_bfloat16 l3 = __float2bfloat16(v.w - __bfloat162float(h3));
    ((__nv_bfloat162*)hi)[idx * 2]     = __nv_bfloat162(h0, h1);
    ((__nv_bfloat162*)hi)[idx * 2 + 1] = __nv_bfloat162(h2, h3);
    ((__nv_bfloat162*)lo)[idx * 2]     = __nv_bfloat162(l0, l1);
    ((__nv_bfloat162*)lo)[idx * 2 + 1] = __nv_bfloat162(l2, l3);
}

// ---------------------------------------------------------------------------
// W[K][N] -> Wt[N][K] bf16 hi/lo split (tiled transpose)
// ---------------------------------------------------------------------------
__global__ __launch_bounds__(256) void tsplit_k(const float* __restrict__ W,
                                                __nv_bfloat16* __restrict__ hi,
                                                __nv_bfloat16* __restrict__ lo,
                                                int K, int N)
{
    __shared__ float t[32][33];
    const int n0 = blockIdx.x * 32, k0 = blockIdx.y * 32;
    const int txi = threadIdx.x, tyi = threadIdx.y;
#pragma unroll
    for (int i = 0; i < 4; i++)
        t[tyi + i * 8][txi] = W[(size_t)(k0 + tyi + i * 8) * N + n0 + txi];
    __syncthreads();
#pragma unroll
    for (int i = 0; i < 4; i++) {
        float v = t[txi][tyi + i * 8];
        __nv_bfloat16 h = __float2bfloat16(v);
        __nv_bfloat16 l = __float2bfloat16(v - __bfloat162float(h));
        size_t o = (size_t)(n0 + tyi + i * 8) * K + k0 + txi;
        hi[o] = h;
        lo[o] = l;
    }
}

// ---------------------------------------------------------------------------
// mma.sync split-bf16 GEMM with 2-stage cp.async pipeline (unchanged, measured)
// ---------------------------------------------------------------------------
#define GBM 128
#define GBN 128
#define GBK 64
#define LROW 144
#define TILE_B (128 * LROW)        // 18432
#define STG_B  (4 * TILE_B)        // 73728 per stage
#define GEMM_SMEM (2 * STG_B)      // 147456

__global__ __launch_bounds__(256) void gemm_mma(
    const __nv_bfloat16* __restrict__ Ah, const __nv_bfloat16* __restrict__ Al,
    const __nv_bfloat16* __restrict__ Bh, const __nv_bfloat16* __restrict__ Bl,
    const float* __restrict__ bias, float* __restrict__ C,
    int M, int N, int K)
{
    extern __shared__ __align__(128) char sm[];
    const uint32_t sb = smem_u32(sm);
    const int tid = threadIdx.x;
    const int wid = tid >> 5, lane = tid & 31;
    const int wm = wid & 3, wn = wid >> 2;
    const int bm = blockIdx.y * GBM, bn = blockIdx.x * GBN;

    float acc[2][8][4];
#pragma unroll
    for (int mi = 0; mi < 2; mi++)
#pragma unroll
        for (int ni = 0; ni < 8; ni++)
#pragma unroll
            for (int c = 0; c < 4; c++) acc[mi][ni][c] = 0.f;

    const uint32_t aRow = (uint32_t)(wm * 32 + (lane & 15));
    const uint32_t aKb  = (uint32_t)((lane >> 4) * 16);
    const uint32_t bRow = (uint32_t)(wn * 64 + (lane & 7) + ((lane >> 4) << 3));
    const uint32_t bKb  = (uint32_t)(((lane >> 3) & 1) * 16);

    const int KT = K / GBK;

#define LOAD_STAGE(s, k0)                                                      \
    do {                                                                       \
        uint32_t sbase = sb + (uint32_t)(s) * STG_B;                           \
        _Pragma("unroll")                                                      \
        for (int it = 0; it < 4; it++) {                                       \
            int idx = tid + it * 256;                                          \
            int r = idx >> 3, c8 = idx & 7;                                    \
            uint32_t so = (uint32_t)(r * LROW + c8 * 16);                      \
            const __nv_bfloat16* pa = Ah + (size_t)(bm + r) * K + (k0) + c8 * 8; \
            const __nv_bfloat16* pl = Al + (size_t)(bm + r) * K + (k0) + c8 * 8; \
            const __nv_bfloat16* pb = Bh + (size_t)(bn + r) * K + (k0) + c8 * 8; \
            const __nv_bfloat16* pc = Bl + (size_t)(bn + r) * K + (k0) + c8 * 8; \
            CP_ASYNC16(sbase + so, pa);                                        \
            CP_ASYNC16(sbase + TILE_B + so, pl);                               \
            CP_ASYNC16(sbase + 2 * TILE_B + so, pb);                           \
            CP_ASYNC16(sbase + 3 * TILE_B + so, pc);                           \
        }                                                                      \
    } while (0)

    LOAD_STAGE(0, 0);
    CP_COMMIT();

    for (int kt = 0; kt < KT; kt++) {
        if (kt + 1 < KT) {
            LOAD_STAGE((kt + 1) & 1, (kt + 1) * GBK);
            CP_COMMIT();
            CP_WAIT(1);
        } else {
            CP_WAIT(0);
        }
        __syncthreads();

        const uint32_t stg = sb + (uint32_t)(kt & 1) * STG_B;
#pragma unroll
        for (int ks = 0; ks < 4; ks++) {
            uint32_t ah[2][4], al[2][4];
#pragma unroll
            for (int mi = 0; mi < 2; mi++) {
                uint32_t ad = stg + (aRow + mi * 16) * LROW + ks * 32 + aKb;
                LDSM_X4(ah[mi][0], ah[mi][1], ah[mi][2], ah[mi][3], ad);
                LDSM_X4(al[mi][0], al[mi][1], al[mi][2], al[mi][3], ad + TILE_B);
            }
#pragma unroll
            for (int np = 0; np < 4; np++) {
                uint32_t bd = stg + 2 * TILE_B + (bRow + np * 16) * LROW + ks * 32 + bKb;
                uint32_t bh0, bh1, bh2, bh3, bl0, bl1, bl2, bl3;
                LDSM_X4(bh0, bh1, bh2, bh3, bd);
                LDSM_X4(bl0, bl1, bl2, bl3, bd + TILE_B);
#pragma unroll
                for (int mi = 0; mi < 2; mi++) {
                    float* d0 = acc[mi][np * 2];
                    float* d1 = acc[mi][np * 2 + 1];
                    MMA_BF16(d0, ah[mi][0], ah[mi][1], ah[mi][2], ah[mi][3], bh0, bh1);
                    MMA_BF16(d0, al[mi][0], al[mi][1], al[mi][2], al[mi][3], bh0, bh1);
                    MMA_BF16(d0, ah[mi][0], ah[mi][1], ah[mi][2], ah[mi][3], bl0, bl1);
                    MMA_BF16(d1, ah[mi][0], ah[mi][1], ah[mi][2], ah[mi][3], bh2, bh3);
                    MMA_BF16(d1, al[mi][0], al[mi][1], al[mi][2], al[mi][3], bh2, bh3);
                    MMA_BF16(d1, ah[mi][0], ah[mi][1], ah[mi][2], ah[mi][3], bl2, bl3);
                }
            }
        }
        __syncthreads();
    }

    const int gr = lane >> 2, qc = lane & 3;
#pragma unroll
    for (int mi = 0; mi < 2; mi++) {
#pragma unroll
        for (int ni = 0; ni < 8; ni++) {
            int row0 = bm + wm * 32 + mi * 16 + gr;
            int col = bn + wn * 64 + ni * 8 + qc * 2;
            float b0 = bias[col], b1 = bias[col + 1];
            float2 v0, v1;
            v0.x = acc[mi][ni][0] + b0;
            v0.y = acc[mi][ni][1] + b1;
            v1.x = acc[mi][ni][2] + b0;
            v1.y = acc[mi][ni][3] + b1;
            *(float2*)(C + (size_t)row0 * N + col) = v0;
            *(float2*)(C + (size_t)(row0 + 8) * N + col) = v1;
        }
    }
}

// ---------------------------------------------------------------------------
// tf32 flash attention, 2-stage cp.async K/V double-buffer, raw-fp32 operands
// (mma truncates to tf32). Grid (T/64, H, B), 128 threads (4 warps).
// Output: fused bf16 hi/lo split (feeds proj gemm directly).
// smem (floats): Qs 64x72 | K0 64x72 | V0 64x72 | K1 64x72 | V1 64x72 | Ps 64x72
// ---------------------------------------------------------------------------
#define AT_PAD 72
#define AT_TILE (64 * AT_PAD)              // floats per tile
#define AT_TILE_B (AT_TILE * 4)            // 18432 bytes
#define ATTN_SMEM (6 * AT_TILE_B)          // 110592 bytes

__global__ __launch_bounds__(128) void attn_mma(const float* __restrict__ qkv,
                                                __nv_bfloat16* __restrict__ yh,
                                                __nv_bfloat16* __restrict__ yl)
{
    extern __shared__ __align__(128) float smf[];
    uint32_t* Qs = (uint32_t*)smf;
    uint32_t* Ps = Qs + 5 * AT_TILE;
    const uint32_t sb = smem_u32(smf);
    const uint32_t kv0 = sb + AT_TILE_B;            // K0; V0 at +AT_TILE_B

    const int tid = threadIdx.x;
    const int w = tid >> 5, lane = tid & 31;
    const int g = lane >> 2, q = lane & 3;
    const int q0 = blockIdx.x * 64;
    const int h = blockIdx.y;
    const int b = blockIdx.z;
    const size_t base = (size_t)b * T_ * QKVC;
    const int qoff = h * HD_;
    const int koff = C_ + h * HD_;
    const int voff = 2 * C_ + h * HD_;

    // Q tile (scaled by 1/8 — exact), raw fp32 bits
    for (int i = tid; i < 64 * 16; i += 128) {
        int r = i >> 4, c4 = (i & 15) << 2;
        float4 v = *(const float4*)(qkv + base + (size_t)(q0 + r) * QKVC + qoff + c4);
        Qs[r * AT_PAD + c4 + 0] = __float_as_uint(v.x * 0.125f);
        Qs[r * AT_PAD + c4 + 1] = __float_as_uint(v.y * 0.125f);
        Qs[r * AT_PAD + c4 + 2] = __float_as_uint(v.z * 0.125f);
        Qs[r * AT_PAD + c4 + 3] = __float_as_uint(v.w * 0.125f);
    }

    // K/V stage load: 64 rows x 256B each for K and V -> 16 cp.async per thread
#define KV_LOAD(s, t0)                                                        \
    do {                                                                      \
        uint32_t kb = kv0 + (uint32_t)(s) * (2 * AT_TILE_B);                  \
        _Pragma("unroll")                                                     \
        for (int j = 0; j < 8; j++) {                                         \
            int i = tid + j * 128;                                            \
            int r = i >> 4, c = i & 15;                                       \
            const float* rowp = qkv + base + (size_t)((t0) + r) * QKVC;       \
            uint32_t so = (uint32_t)(r * (AT_PAD * 4) + c * 16);              \
            CP_ASYNC16(kb + so, rowp + koff + c * 4);                         \
            CP_ASYNC16(kb + AT_TILE_B + so, rowp + voff + c * 4);             \
        }                                                                     \
    } while (0)

    float m0 = -1e30f, m1 = -1e30f, l0 = 0.f, l1 = 0.f;
    float o[8][4];
#pragma unroll
    for (int nt = 0; nt < 8; nt++)
#pragma unroll
        for (int c = 0; c < 4; c++) o[nt][c] = 0.f;

    const int rA0 = (16 * w + g) * AT_PAD;
    const int rA1 = (16 * w + g + 8) * AT_PAD;

    KV_LOAD(0, 0);
    CP_COMMIT();

    for (int kt = 0; kt < T_ / 64; kt++) {
        if (kt + 1 < T_ / 64) {
            KV_LOAD((kt + 1) & 1, (kt + 1) * 64);
            CP_COMMIT();
            CP_WAIT(1);
        } else {
            CP_WAIT(0);
        }
        __syncthreads();

        uint32_t* Ks = (uint32_t*)smf + AT_TILE + (kt & 1) * 2 * AT_TILE;
        uint32_t* Vs = Ks + AT_TILE;

        // S = Q K^T
        float s[8][4];
#pragma unroll
        for (int nt = 0; nt < 8; nt++)
#pragma unroll
            for (int c = 0; c < 4; c++) s[nt][c] = 0.f;

#pragma unroll
        for (int kk = 0; kk < 8; kk++) {
            uint32_t a0 = Qs[rA0 + q + 8 * kk];
            uint32_t a1 = Qs[rA1 + q + 8 * kk];
            uint32_t a2 = Qs[rA0 + q + 4 + 8 * kk];
            uint32_t a3 = Qs[rA1 + q + 4 + 8 * kk];
#pragma unroll
            for (int nt = 0; nt < 8; nt++) {
                uint32_t b0 = Ks[(nt * 8 + g) * AT_PAD + q + 8 * kk];
                uint32_t b1 = Ks[(nt * 8 + g) * AT_PAD + q + 4 + 8 * kk];
                MMA_TF32(s[nt], a0, a1, a2, a3, b0, b1);
            }
        }

        // online softmax (rows g / g+8, warp-local across lanes 4g..4g+3)
        float mt0 = -1e30f, mt1 = -1e30f;
#pragma unroll
        for (int nt = 0; nt < 8; nt++) {
            mt0 = fmaxf(mt0, fmaxf(s[nt][0], s[nt][1]));
            mt1 = fmaxf(mt1, fmaxf(s[nt][2], s[nt][3]));
        }
#pragma unroll
        for (int off = 1; off <= 2; off <<= 1) {
            mt0 = fmaxf(mt0, __shfl_xor_sync(0xffffffffu, mt0, off));
            mt1 = fmaxf(mt1, __shfl_xor_sync(0xffffffffu, mt1, off));
        }
        float mn0 = fmaxf(m0, mt0), mn1 = fmaxf(m1, mt1);
        float al0 = __expf(m0 - mn0), al1 = __expf(m1 - mn1);
        m0 = mn0;
        m1 = mn1;

        float lt0 = 0.f, lt1 = 0.f;
#pragma unroll
        for (int nt = 0; nt < 8; nt++) {
            float p0 = __expf(s[nt][0] - mn0);
            float p1 = __expf(s[nt][1] - mn0);
            float p2 = __expf(s[nt][2] - mn1);
            float p3 = __expf(s[nt][3] - mn1);
            lt0 += p0 + p1;
            lt1 += p2 + p3;
            Ps[rA0 + nt * 8 + 2 * q]     = __float_as_uint(p0);
            Ps[rA0 + nt * 8 + 2 * q + 1] = __float_as_uint(p1);
            Ps[rA1 + nt * 8 + 2 * q]     = __float_as_uint(p2);
            Ps[rA1 + nt * 8 + 2 * q + 1] = __float_as_uint(p3);
        }
#pragma unroll
        for (int off = 1; off <= 2; off <<= 1) {
            lt0 += __shfl_xor_sync(0xffffffffu, lt0, off);
            lt1 += __shfl_xor_sync(0xffffffffu, lt1, off);
        }
        l0 = l0 * al0 + lt0;
        l1 = l1 * al1 + lt1;

#pragma unroll
        for (int nt = 0; nt < 8; nt++) {
            o[nt][0] *= al0;
            o[nt][1] *= al0;
            o[nt][2] *= al1;
            o[nt][3] *= al1;
        }
        __syncwarp();   // P rows are warp-private

        // O += P V
#pragma unroll
        for (int kk = 0; kk < 8; kk++) {
            uint32_t a0 = Ps[rA0 + q + 8 * kk];
            uint32_t a1 = Ps[rA1 + q + 8 * kk];
            uint32_t a2 = Ps[rA0 + q + 4 + 8 * kk];
            uint32_t a3 = Ps[rA1 + q + 4 + 8 * kk];
#pragma unroll
            for (int nt = 0; nt < 8; nt++) {
                uint32_t b0 = Vs[(8 * kk + q) * AT_PAD + nt * 8 + g];
                uint32_t b1 = Vs[(8 * kk + q + 4) * AT_PAD + nt * 8 + g];
                MMA_TF32(o[nt], a0, a1, a2, a3, b0, b1);
            }
        }
        __syncthreads();   // stage reuse 2 iters later
    }

    // normalize + fused bf16 hi/lo split store
    const float inv0 = 1.f / l0, inv1 = 1.f / l1;
    const int r0 = b * T_ + q0 + 16 * w + g;
#pragma unroll
    for (int nt = 0; nt < 8; nt++) {
        int col = h * HD_ + nt * 8 + 2 * q;
        float v00 = o[nt][0] * inv0, v01 = o[nt][1] * inv0;
        float v10 = o[nt][2] * inv1, v11 = o[nt][3] * inv1;
        __nv_bfloat16 h00 = __float2bfloat16(v00), h01 = __float2bfloat16(v01);
        __nv_bfloat16 h10 = __float2bfloat16(v10), h11 = __float2bfloat16(v11);
        __nv_bfloat16 l00 = __float2bfloat16(v00 - __bfloat162float(h00));
        __nv_bfloat16 l01 = __float2bfloat16(v01 - __bfloat162float(h01));
        __nv_bfloat16 l10 = __float2bfloat16(v10 - __bfloat162float(h10));
        __nv_bfloat16 l11 = __float2bfloat16(v11 - __bfloat162float(h11));
        *(__nv_bfloat162*)(yh + (size_t)r0 * C_ + col)       = __nv_bfloat162(h00, h01);
        *(__nv_bfloat162*)(yl + (size_t)r0 * C_ + col)       = __nv_bfloat162(l00, l01);
        *(__nv_bfloat162*)(yh + (size_t)(r0 + 8) * C_ + col) = __nv_bfloat162(h10, h11);
        *(__nv_bfloat162*)(yl + (size_t)(r0 + 8) * C_ + col) = __nv_bfloat162(l10, l11);
    }
}

extern "C" void kernel_launch(void* const* d_in, const int* in_sizes, int n_in,
                              void* d_out, int out_size)
{
    (void)in_sizes; (void)n_in; (void)out_size;
    const float* x      = (const float*)d_in[0];
    const float* W_attn = (const float*)d_in[1];
    const float* b_attn = (const float*)d_in[2];
    const float* W_proj = (const float*)d_in[3];
    const float* b_proj = (const float*)d_in[4];
    float* out = (float*)d_out;

    float* qkv = nullptr;
    __nv_bfloat16 *xh, *xl, *wah, *wal, *wph, *wpl;
    cudaGetSymbolAddress((void**)&qkv, g_qkv);
    cudaGetSymbolAddress((void**)&xh, g_xh);
    cudaGetSymbolAddress((void**)&xl, g_xl);
    cudaGetSymbolAddress((void**)&wah, g_wah);
    cudaGetSymbolAddress((void**)&wal, g_wal);
    cudaGetSymbolAddress((void**)&wph, g_wph);
    cudaGetSymbolAddress((void**)&wpl, g_wpl);

    cudaFuncSetAttribute(attn_mma, cudaFuncAttributeMaxDynamicSharedMemorySize, ATTN_SMEM);
    cudaFuncSetAttribute(gemm_mma, cudaFuncAttributeMaxDynamicSharedMemorySize, GEMM_SMEM);

    const int n4x = (BT * C_) / 4;

    // split inputs to bf16 hi/lo (weights transposed to [N][K])
    split_k<<<(n4x + 255) / 256, 256>>>(x, xh, xl, n4x);
    tsplit_k<<<dim3(QKVC / 32, C_ / 32), dim3(32, 8)>>>(W_attn, wah, wal, C_, QKVC);
    tsplit_k<<<dim3(C_ / 32, C_ / 32), dim3(32, 8)>>>(W_proj, wph, wpl, C_, C_);

    // 1) qkv = x @ W_attn + b_attn  (bf16-split HMMA, cp.async pipelined)
    gemm_mma<<<dim3(QKVC / GBN, BT / GBM), 256, GEMM_SMEM>>>(
        xh, xl, wah, wal, b_attn, qkv, BT, QKVC, C_);

    // 2) y = SDPA(q,k,v) (tf32 HMMA flash, cp.async K/V, fused hi/lo output)
    attn_mma<<<dim3(T_ / 64, H_, B_), 128, ATTN_SMEM>>>(qkv, xh, xl);

    // 3) out = y @ W_proj + b_proj  (bf16-split HMMA, reads fused split)
    gemm_mma<<<dim3(C_ / GBN, BT / GBM), 256, GEMM_SMEM>>>(
        xh, xl, wph, wpl, b_proj, out, BT, C_, C_);
}